// round 6
// baseline (speedup 1.0000x reference)
#include <cuda_runtime.h>
#include <cuda_bf16.h>
#include <math.h>
#include <stdint.h>

#define N_TOKENS 65536
#define EMB_DIM  128
#define NUM_EMB  1024

// Output tuple flattened scalar-wise in reference-return order:
// (e_latent_loss, quantized_st[N,D], perplexity, encodings[N,K])
#define OUT_LOSS 0
#define OUT_Q    1
#define OUT_PERP (1 + N_TOKENS * EMB_DIM)        // 8388609
#define OUT_ENC  (2 + N_TOKENS * EMB_DIM)        // 8388610 (even -> 8B-aligned)

#define BM   128
#define NBLK (N_TOKENS / BM)     // 512
#define NTILES 8                 // 8 code tiles of 128
#define CAP  8                   // candidates per (token, tig) list

// smem byte offsets (dynamic, base 16B-aligned)
#define SM_T     0        // 34816: 128 rows x 272B  (A tile, then B tiles)
#define SM_CAND  34816    // 8192: uint16 cand[128*4][CAP]
#define SM_CNT   43008    // 1024: uint16 cnt[128*4]  (stored as u16, 512 used)
#define SM_SXD   44032    // 1024: double sx[128]
#define SM_SBK   45056    // 512:  int bk[128]
#define SM_LRED  45568    // 2048: double lred[256]
#define SM_LACC  47616    // 2048: double lacc[256]
#define DSMEM    49664

#define ROWB 272          // 136 bf16 per row: conflict-free fragment loads

__device__ __align__(16) __nv_bfloat16 g_ebf[NUM_EMB * EMB_DIM]; // bf16 codebook
__device__ float  g_be[NUM_EMB];     // fl32 of exact ||e_k||^2
__device__ int    g_hist[NUM_EMB];   // code counts
__device__ double g_lpart[NBLK];     // per-block loss partials
__device__ unsigned int g_done;      // last-block-done counter

// baseline-PTX tensor op (compute_103-safe): m16n8k16 bf16 -> f32
__device__ __forceinline__ void mma16816(float* d,
                                         uint32_t a0, uint32_t a1,
                                         uint32_t a2, uint32_t a3,
                                         uint32_t b0, uint32_t b1) {
    asm volatile(
        "mma.sync.aligned.m16n8k16.row.col.f32.bf16.bf16.f32 "
        "{%0,%1,%2,%3}, {%4,%5,%6,%7}, {%8,%9}, {%0,%1,%2,%3};"
        : "+f"(d[0]), "+f"(d[1]), "+f"(d[2]), "+f"(d[3])
        : "r"(a0), "r"(a1), "r"(a2), "r"(a3), "r"(b0), "r"(b1));
}

// ---------------------------------------------------------------------------
// prep: bf16 codebook + exact fp32 norms + zero hist/done. Warp per code.
// ---------------------------------------------------------------------------
__global__ void vq_prep_kernel(const float* __restrict__ emb) {
    const int gtid = blockIdx.x * 256 + threadIdx.x;   // 32768 threads
    const int code = gtid >> 5, lane = gtid & 31;
    float4 v = ((const float4*)(emb + (size_t)code * EMB_DIM))[lane];
    double s;
    { double a = v.x, b = v.y, c = v.z, d = v.w; s = a*a + b*b + c*c + d*d; }
    __nv_bfloat162 p0 = __float22bfloat162_rn(make_float2(v.x, v.y));
    __nv_bfloat162 p1 = __float22bfloat162_rn(make_float2(v.z, v.w));
    uint2 u; u.x = *(unsigned*)&p0; u.y = *(unsigned*)&p1;
    *(uint2*)&g_ebf[(size_t)code * EMB_DIM + lane * 4] = u;
#pragma unroll
    for (int off = 16; off > 0; off >>= 1)
        s += __shfl_down_sync(0xffffffffu, s, off);
    if (lane == 0) { g_be[code] = (float)s; g_hist[code] = 0; }
    if (gtid == 0) g_done = 0;
}

// ---------------------------------------------------------------------------
// main: HMMA (mma.sync bf16) screening GEMM + margin-certified candidates +
// exact fp32 rescore (R3 bit-identical chain) + fused outputs.
// ---------------------------------------------------------------------------
__global__ __launch_bounds__(256, 2)
void vq_main_kernel(const float* __restrict__ x,
                    const float* __restrict__ emb,
                    float* __restrict__ out)
{
    extern __shared__ __align__(16) char dsm[];
    char*      sT   = dsm + SM_T;
    uint16_t*  cand = (uint16_t*)(dsm + SM_CAND);
    uint16_t*  cnts = (uint16_t*)(dsm + SM_CNT);
    double*    sxd  = (double*)(dsm + SM_SXD);
    int*       s_bk = (int*)(dsm + SM_SBK);
    double*    lred = (double*)(dsm + SM_LRED);
    double*    lacc = (double*)(dsm + SM_LACC);

    const int tid  = threadIdx.x;    // 256
    const int wid  = tid >> 5;       // 8 warps; warp owns tokens 16w..16w+15
    const int lane = tid & 31;
    const int gID  = lane >> 2;      // 0..7
    const int tig  = lane & 3;       // 0..3
    const int m0   = blockIdx.x * BM;

    // ---- zero this block's one-hot rows (big DRAM op, overlaps all) ----
    {
        float2* enc2 = (float2*)(out + OUT_ENC);
        size_t base = (size_t)m0 * (NUM_EMB / 2);
        for (int i = tid; i < BM * NUM_EMB / 2; i += 256)
            enc2[base + i] = make_float2(0.f, 0.f);
    }

    // ---- A tile: x rows -> bf16 smem (row-major, 272B stride); sx double ----
    if (tid < 128) {
        const float4* xr = (const float4*)(x + (size_t)(m0 + tid) * EMB_DIM);
        char* row = sT + tid * ROWB;
        double sx = 0.0;
#pragma unroll
        for (int c = 0; c < 32; c++) {
            float4 v = xr[c];
            __nv_bfloat162 p0 = __float22bfloat162_rn(make_float2(v.x, v.y));
            __nv_bfloat162 p1 = __float22bfloat162_rn(make_float2(v.z, v.w));
            uint2 u; u.x = *(unsigned*)&p0; u.y = *(unsigned*)&p1;
            *(uint2*)(row + c * 8) = u;
            double a = v.x, b = v.y, cc = v.z, d = v.w;
            sx += a * a; sx += b * b; sx += cc * cc; sx += d * d;
        }
        sxd[tid] = sx;
    }
    __syncthreads();

    // ---- load this warp's A fragments into registers (kept all kernel) ----
    uint32_t afr[32];
    {
        const char* r0 = sT + (wid * 16 + gID) * ROWB + 4 * tig;  // token row gID
        const char* r1 = r0 + 8 * ROWB;                           // token row gID+8
#pragma unroll
        for (int s = 0; s < 8; s++) {
            afr[4*s+0] = *(const uint32_t*)(r0 + 32 * s);
            afr[4*s+1] = *(const uint32_t*)(r1 + 32 * s);
            afr[4*s+2] = *(const uint32_t*)(r0 + 32 * s + 16);
            afr[4*s+3] = *(const uint32_t*)(r1 + 32 * s + 16);
        }
    }
    const int tok0 = wid * 16 + gID;        // local token of acc rows 0..7
    const int tok1 = tok0 + 8;
    const float d0 = 2.5e-4f * sqrtf((float)sxd[tok0]) + 2e-4f;
    const float d1 = 2.5e-4f * sqrtf((float)sxd[tok1]) + 2e-4f;
    float rm0 = INFINITY, rm1 = INFINITY;
    int   cnt0 = 0, cnt1 = 0;
    uint16_t* L0 = cand + (tok0 * 4 + tig) * CAP;
    uint16_t* L1 = cand + (tok1 * 4 + tig) * CAP;
    __syncthreads();   // A fragments consumed; sT free for B tiles

    // ---- screening loop over 8 code tiles of 128 ----
    for (int t = 0; t < NTILES; t++) {
        // load B tile: 2 threads per code row, uint4 (8 bf16) x 8
        {
            const int r2 = tid >> 1, kh = tid & 1;
            const uint4* src = (const uint4*)(g_ebf +
                ((size_t)(t * 128 + r2) * EMB_DIM + kh * 64));
            char* dst = sT + r2 * ROWB + kh * 128;
#pragma unroll
            for (int j = 0; j < 8; j++)
                *(uint4*)(dst + j * 16) = src[j];
        }
        __syncthreads();

        // 16 n-tiles of 8 codes; process 2 at a time for HMMA ILP
#pragma unroll 2
        for (int nt = 0; nt < 16; nt += 2) {
            const char* pb0 = sT + (nt * 8 + gID) * ROWB + 4 * tig;
            const char* pb1 = pb0 + 8 * ROWB;   // next n-tile (+8 codes)
            float ac0[4] = {0.f, 0.f, 0.f, 0.f};
            float ac1[4] = {0.f, 0.f, 0.f, 0.f};
#pragma unroll
            for (int s = 0; s < 8; s++) {
                uint32_t b00 = *(const uint32_t*)(pb0 + 32 * s);
                uint32_t b01 = *(const uint32_t*)(pb0 + 32 * s + 16);
                uint32_t b10 = *(const uint32_t*)(pb1 + 32 * s);
                uint32_t b11 = *(const uint32_t*)(pb1 + 32 * s + 16);
                mma16816(ac0, afr[4*s], afr[4*s+1], afr[4*s+2], afr[4*s+3], b00, b01);
                mma16816(ac1, afr[4*s], afr[4*s+1], afr[4*s+2], afr[4*s+3], b10, b11);
            }
            // scores + candidate collection for both n-tiles
#pragma unroll
            for (int h = 0; h < 2; h++) {
                const float* ac = h ? ac1 : ac0;
                const int n0 = t * 128 + (nt + h) * 8;
                const int c0 = n0 + 2 * tig;
                float2 be2 = __ldg((const float2*)(g_be + c0));
                float s00 = __fmaf_rn(-2.f, ac[0], be2.x);
                float s01 = __fmaf_rn(-2.f, ac[1], be2.y);
                float s10 = __fmaf_rn(-2.f, ac[2], be2.x);
                float s11 = __fmaf_rn(-2.f, ac[3], be2.y);
                if (s00 - rm0 <= d0) { if (cnt0 < CAP) L0[cnt0] = (uint16_t)c0; cnt0++; }
                rm0 = fminf(rm0, s00);
                if (s01 - rm0 <= d0) { if (cnt0 < CAP) L0[cnt0] = (uint16_t)(c0+1); cnt0++; }
                rm0 = fminf(rm0, s01);
                if (s10 - rm1 <= d1) { if (cnt1 < CAP) L1[cnt1] = (uint16_t)c0; cnt1++; }
                rm1 = fminf(rm1, s10);
                if (s11 - rm1 <= d1) { if (cnt1 < CAP) L1[cnt1] = (uint16_t)(c0+1); cnt1++; }
                rm1 = fminf(rm1, s11);
            }
        }
        __syncthreads();   // all b reads done before next tile overwrite
    }
    cnts[tok0 * 4 + tig] = (uint16_t)cnt0;
    cnts[tok1 * 4 + tig] = (uint16_t)cnt1;
    __syncthreads();

    // ---- phase 2: exact rescore (R3 bit-exact arithmetic) ----
    if (tid < 128) {
        const int row = m0 + tid;
        const float sxe = (float)sxd[tid];
        const float* xr = x + (size_t)row * EMB_DIM;
        float bv = INFINITY;
        int   bk = 1 << 30;
        bool ovf = false;
#pragma unroll
        for (int li = 0; li < 4; li++)
            if (cnts[tid * 4 + li] > CAP) ovf = true;
        if (ovf) {
            // overflow fallback (probability ~0): full exact scan
            for (int k = 0; k < NUM_EMB; k++) {
                const float* er = emb + (size_t)k * EMB_DIM;
                float dot = 0.f;
#pragma unroll 16
                for (int i = 0; i < EMB_DIM; i++)
                    dot = __fmaf_rn(xr[i], er[i], dot);
                float d = __fsub_rn(__fadd_rn(sxe, g_be[k]),
                                    __fmul_rn(2.0f, dot));
                if (d < bv || (d == bv && k < bk)) { bv = d; bk = k; }
            }
        } else {
#pragma unroll
            for (int li = 0; li < 4; li++) {
                const uint16_t* ls = cand + (tid * 4 + li) * CAP;
                const int nc = cnts[tid * 4 + li];
                for (int i = 0; i < nc; i++) {
                    const int k = ls[i];
                    const float* er = emb + (size_t)k * EMB_DIM;
                    float dot = 0.f;
#pragma unroll 16
                    for (int q = 0; q < EMB_DIM; q++)
                        dot = __fmaf_rn(xr[q], er[q], dot);
                    float d = __fsub_rn(__fadd_rn(sxe, g_be[k]),
                                        __fmul_rn(2.0f, dot));
                    if (d < bv || (d == bv && k < bk)) { bv = d; bk = k; }
                }
            }
        }
        s_bk[tid] = bk;
        out[(size_t)OUT_ENC + (size_t)row * NUM_EMB + bk] = 1.0f;
        atomicAdd(&g_hist[bk], 1);   // integer atomic: deterministic
    }
    __syncthreads();

    // ---- cooperative coalesced quantized_st + loss (32-bit stores) ----
    double lsum = 0.0;
    float* oq = out + OUT_Q + (size_t)m0 * EMB_DIM;
    const float* xq = x + (size_t)m0 * EMB_DIM;
    for (int e = tid; e < BM * EMB_DIM; e += 256) {
        const int row = e >> 7;
        const int col = e & 127;
        const float xv = xq[e];
        const float qv = emb[(size_t)s_bk[row] * EMB_DIM + col];
        const float d  = __fsub_rn(qv, xv);
        oq[e] = __fadd_rn(xv, d);        // fl(x + fl(q-x)), exact STE math
        lsum += (double)d * (double)d;
    }
    lred[tid] = lsum;
    __syncthreads();
    for (int s = 128; s > 0; s >>= 1) {
        if (tid < s) lred[tid] += lred[tid + s];
        __syncthreads();
    }
    if (tid == 0) g_lpart[blockIdx.x] = lred[0];

    // ---- last block computes the scalars (fused finalize) ----
    __shared__ bool is_last;
    __threadfence();
    if (tid == 0) {
        unsigned v = atomicAdd(&g_done, 1u);
        is_last = (v == NBLK - 1);
    }
    __syncthreads();
    if (!is_last) return;

    double ent = 0.0;
#pragma unroll
    for (int b = 0; b < 4; b++) {
        double pr = (double)g_hist[tid * 4 + b] / (double)N_TOKENS;
        ent += pr * log(pr + 1e-10);
    }
    double ls = 0.0;
#pragma unroll
    for (int b = 0; b < 2; b++) ls += g_lpart[tid * 2 + b];
    lred[tid] = ent;
    lacc[tid] = ls;
    __syncthreads();
    for (int s = 128; s > 0; s >>= 1) {
        if (tid < s) { lred[tid] += lred[tid + s]; lacc[tid] += lacc[tid + s]; }
        __syncthreads();
    }
    if (tid == 0) {
        out[OUT_PERP] = (float)exp(-lred[0]);
        out[OUT_LOSS] = (float)(lacc[0] / ((double)N_TOKENS * (double)EMB_DIM));
    }
}

// ---------------------------------------------------------------------------
extern "C" void kernel_launch(void* const* d_in, const int* in_sizes, int n_in,
                              void* d_out, int out_size) {
    const float* x   = (const float*)d_in[0];   // inputs [65536,128]
    const float* emb = (const float*)d_in[1];   // emb_w  [1024,128]
    float* out = (float*)d_out;

    cudaFuncSetAttribute(vq_main_kernel,
                         cudaFuncAttributeMaxDynamicSharedMemorySize, DSMEM);
    vq_prep_kernel<<<NUM_EMB * 32 / 256, 256>>>(emb);
    vq_main_kernel<<<NBLK, 256, DSMEM>>>(x, emb, out);
}

// round 7
// speedup vs baseline: 13.9104x; 13.9104x over previous
#include <cuda_runtime.h>
#include <cuda_bf16.h>
#include <math.h>
#include <stdint.h>

#define N_TOKENS 65536
#define EMB_DIM  128
#define NUM_EMB  1024

// Output tuple flattened scalar-wise in reference-return order:
// (e_latent_loss, quantized_st[N,D], perplexity, encodings[N,K])
#define OUT_LOSS 0
#define OUT_Q    1
#define OUT_PERP (1 + N_TOKENS * EMB_DIM)        // 8388609
#define OUT_ENC  (2 + N_TOKENS * EMB_DIM)        // 8388610 (even -> 8B-aligned)

#define BM   128
#define NBLK (N_TOKENS / BM)     // 512
#define NTILES 8                 // 8 code tiles of 128
#define CAP  8                   // candidates per (token, tig) list

// smem byte offsets (dynamic, base 16B-aligned)
#define SM_T     0        // 34816: 128 rows x 272B  (A tile, then B tiles)
#define SM_CAND  34816    // 8192: uint16 cand[128*4][CAP]
#define SM_CNT   43008    // 1024: uint16 cnt[128*4]
#define SM_SXD   44032    // 1024: double sx[128]
#define SM_SBK   45056    // 512:  int bk[128]
#define SM_LRED  45568    // 2048: double lred[256]
#define SM_LACC  47616    // 2048: double lacc[256]
#define DSMEM    49664

#define ROWB 272          // 136 bf16 per row: conflict-free fragment loads

__device__ __align__(16) __nv_bfloat16 g_ebf[NUM_EMB * EMB_DIM]; // bf16 codebook
__device__ float  g_be[NUM_EMB];     // fl32 of exact ||e_k||^2
__device__ int    g_hist[NUM_EMB];   // code counts
__device__ double g_lpart[NBLK];     // per-block loss partials
__device__ unsigned int g_done;      // last-block-done counter

// baseline-PTX tensor op (compute_103-safe): m16n8k16 bf16 -> f32
__device__ __forceinline__ void mma16816(float* d,
                                         uint32_t a0, uint32_t a1,
                                         uint32_t a2, uint32_t a3,
                                         uint32_t b0, uint32_t b1) {
    asm volatile(
        "mma.sync.aligned.m16n8k16.row.col.f32.bf16.bf16.f32 "
        "{%0,%1,%2,%3}, {%4,%5,%6,%7}, {%8,%9}, {%0,%1,%2,%3};"
        : "+f"(d[0]), "+f"(d[1]), "+f"(d[2]), "+f"(d[3])
        : "r"(a0), "r"(a1), "r"(a2), "r"(a3), "r"(b0), "r"(b1));
}

// exact sequential-k fp32 dot (reference accumulation order), float4 loads
__device__ __forceinline__ float exact_dot(const float* __restrict__ xr,
                                           const float* __restrict__ er) {
    const float4* x4 = (const float4*)xr;
    const float4* e4 = (const float4*)er;
    float dot = 0.f;
#pragma unroll
    for (int q = 0; q < EMB_DIM / 4; q++) {
        float4 xv = x4[q], ev = e4[q];
        dot = __fmaf_rn(xv.x, ev.x, dot);
        dot = __fmaf_rn(xv.y, ev.y, dot);
        dot = __fmaf_rn(xv.z, ev.z, dot);
        dot = __fmaf_rn(xv.w, ev.w, dot);
    }
    return dot;
}

// ---------------------------------------------------------------------------
// prep: bf16 codebook + exact fp32 norms + zero hist/done. Warp per code.
// ---------------------------------------------------------------------------
__global__ void vq_prep_kernel(const float* __restrict__ emb) {
    const int gtid = blockIdx.x * 256 + threadIdx.x;   // 32768 threads
    const int code = gtid >> 5, lane = gtid & 31;
    float4 v = ((const float4*)(emb + (size_t)code * EMB_DIM))[lane];
    double s;
    { double a = v.x, b = v.y, c = v.z, d = v.w; s = a*a + b*b + c*c + d*d; }
    __nv_bfloat162 p0 = __float22bfloat162_rn(make_float2(v.x, v.y));
    __nv_bfloat162 p1 = __float22bfloat162_rn(make_float2(v.z, v.w));
    uint2 u; u.x = *(unsigned*)&p0; u.y = *(unsigned*)&p1;
    *(uint2*)&g_ebf[(size_t)code * EMB_DIM + lane * 4] = u;
#pragma unroll
    for (int off = 16; off > 0; off >>= 1)
        s += __shfl_down_sync(0xffffffffu, s, off);
    if (lane == 0) { g_be[code] = (float)s; g_hist[code] = 0; }
    if (gtid == 0) g_done = 0;
}

// ---------------------------------------------------------------------------
// main: two-pass HMMA screening (pass 0: exact final min of approx scores;
// pass 1: collect codes within certified margin of that min), then exact fp32
// rescore (R3 bit-identical chain) + fused outputs.
// ---------------------------------------------------------------------------
__global__ __launch_bounds__(256, 2)
void vq_main_kernel(const float* __restrict__ x,
                    const float* __restrict__ emb,
                    float* __restrict__ out)
{
    extern __shared__ __align__(16) char dsm[];
    char*      sT   = dsm + SM_T;
    uint16_t*  cand = (uint16_t*)(dsm + SM_CAND);
    uint16_t*  cnts = (uint16_t*)(dsm + SM_CNT);
    double*    sxd  = (double*)(dsm + SM_SXD);
    int*       s_bk = (int*)(dsm + SM_SBK);
    double*    lred = (double*)(dsm + SM_LRED);
    double*    lacc = (double*)(dsm + SM_LACC);

    const int tid  = threadIdx.x;    // 256
    const int wid  = tid >> 5;       // 8 warps; warp owns tokens 16w..16w+15
    const int lane = tid & 31;
    const int gID  = lane >> 2;      // 0..7
    const int tig  = lane & 3;       // 0..3
    const int m0   = blockIdx.x * BM;

    // ---- zero this block's one-hot rows (big DRAM op, overlaps all) ----
    {
        float2* enc2 = (float2*)(out + OUT_ENC);
        size_t base = (size_t)m0 * (NUM_EMB / 2);
        for (int i = tid; i < BM * NUM_EMB / 2; i += 256)
            enc2[base + i] = make_float2(0.f, 0.f);
    }

    // ---- A tile: x rows -> bf16 smem (row-major, 272B stride); sx double ----
    if (tid < 128) {
        const float4* xr = (const float4*)(x + (size_t)(m0 + tid) * EMB_DIM);
        char* row = sT + tid * ROWB;
        double sx = 0.0;
#pragma unroll
        for (int c = 0; c < 32; c++) {
            float4 v = xr[c];
            __nv_bfloat162 p0 = __float22bfloat162_rn(make_float2(v.x, v.y));
            __nv_bfloat162 p1 = __float22bfloat162_rn(make_float2(v.z, v.w));
            uint2 u; u.x = *(unsigned*)&p0; u.y = *(unsigned*)&p1;
            *(uint2*)(row + c * 8) = u;
            double a = v.x, b = v.y, cc = v.z, d = v.w;
            sx += a * a; sx += b * b; sx += cc * cc; sx += d * d;
        }
        sxd[tid] = sx;
    }
    __syncthreads();

    // ---- load this warp's A fragments into registers (kept all kernel) ----
    uint32_t afr[32];
    {
        const char* r0 = sT + (wid * 16 + gID) * ROWB + 4 * tig;  // token row gID
        const char* r1 = r0 + 8 * ROWB;                           // token row gID+8
#pragma unroll
        for (int s = 0; s < 8; s++) {
            afr[4*s+0] = *(const uint32_t*)(r0 + 32 * s);
            afr[4*s+1] = *(const uint32_t*)(r1 + 32 * s);
            afr[4*s+2] = *(const uint32_t*)(r0 + 32 * s + 16);
            afr[4*s+3] = *(const uint32_t*)(r1 + 32 * s + 16);
        }
    }
    const int tok0 = wid * 16 + gID;        // local token of acc rows 0..7
    const int tok1 = tok0 + 8;
    const float d0 = 2.5e-4f * sqrtf((float)sxd[tok0]) + 2e-4f;
    const float d1 = 2.5e-4f * sqrtf((float)sxd[tok1]) + 2e-4f;
    float rm0 = INFINITY, rm1 = INFINITY;
    int   cnt0 = 0, cnt1 = 0;
    uint16_t* L0 = cand + (tok0 * 4 + tig) * CAP;
    uint16_t* L1 = cand + (tok1 * 4 + tig) * CAP;
    __syncthreads();   // A fragments consumed; sT free for B tiles

    // ---- two-pass screening over 8 code tiles of 128 ----
    // pass 0: compute final min of approx scores (no collection)
    // pass 1: identical MMA sequence (bitwise-same scores), collect s <= thr
    for (int pass = 0; pass < 2; pass++) {
        const float thr0 = rm0 + d0;    // inf in pass 0 (unused)
        const float thr1 = rm1 + d1;
        for (int t = 0; t < NTILES; t++) {
            // load B tile: 2 threads per code row, uint4 (8 bf16) x 8
            {
                const int r2 = tid >> 1, kh = tid & 1;
                const uint4* src = (const uint4*)(g_ebf +
                    ((size_t)(t * 128 + r2) * EMB_DIM + kh * 64));
                char* dst = sT + r2 * ROWB + kh * 128;
#pragma unroll
                for (int j = 0; j < 8; j++)
                    *(uint4*)(dst + j * 16) = src[j];
            }
            __syncthreads();

            // 16 n-tiles of 8 codes; 2 at a time for HMMA ILP
#pragma unroll 2
            for (int nt = 0; nt < 16; nt += 2) {
                const char* pb0 = sT + (nt * 8 + gID) * ROWB + 4 * tig;
                const char* pb1 = pb0 + 8 * ROWB;   // next n-tile (+8 codes)
                float ac0[4] = {0.f, 0.f, 0.f, 0.f};
                float ac1[4] = {0.f, 0.f, 0.f, 0.f};
#pragma unroll
                for (int s = 0; s < 8; s++) {
                    uint32_t b00 = *(const uint32_t*)(pb0 + 32 * s);
                    uint32_t b01 = *(const uint32_t*)(pb0 + 32 * s + 16);
                    uint32_t b10 = *(const uint32_t*)(pb1 + 32 * s);
                    uint32_t b11 = *(const uint32_t*)(pb1 + 32 * s + 16);
                    mma16816(ac0, afr[4*s], afr[4*s+1], afr[4*s+2], afr[4*s+3], b00, b01);
                    mma16816(ac1, afr[4*s], afr[4*s+1], afr[4*s+2], afr[4*s+3], b10, b11);
                }
#pragma unroll
                for (int h = 0; h < 2; h++) {
                    const float* ac = h ? ac1 : ac0;
                    const int c0 = t * 128 + (nt + h) * 8 + 2 * tig;
                    float2 be2 = __ldg((const float2*)(g_be + c0));
                    float s00 = __fmaf_rn(-2.f, ac[0], be2.x);
                    float s01 = __fmaf_rn(-2.f, ac[1], be2.y);
                    float s10 = __fmaf_rn(-2.f, ac[2], be2.x);
                    float s11 = __fmaf_rn(-2.f, ac[3], be2.y);
                    if (pass == 0) {
                        rm0 = fminf(rm0, fminf(s00, s01));
                        rm1 = fminf(rm1, fminf(s10, s11));
                    } else {
                        if (s00 <= thr0) { if (cnt0 < CAP) L0[cnt0] = (uint16_t)c0;     cnt0++; }
                        if (s01 <= thr0) { if (cnt0 < CAP) L0[cnt0] = (uint16_t)(c0+1); cnt0++; }
                        if (s10 <= thr1) { if (cnt1 < CAP) L1[cnt1] = (uint16_t)c0;     cnt1++; }
                        if (s11 <= thr1) { if (cnt1 < CAP) L1[cnt1] = (uint16_t)(c0+1); cnt1++; }
                    }
                }
            }
            __syncthreads();   // all b reads done before next tile overwrite
        }
    }
    cnts[tok0 * 4 + tig] = (uint16_t)cnt0;
    cnts[tok1 * 4 + tig] = (uint16_t)cnt1;
    __syncthreads();

    // ---- phase 2: exact rescore (R3 bit-exact arithmetic, float4 loads) ----
    if (tid < 128) {
        const int row = m0 + tid;
        const float sxe = (float)sxd[tid];
        const float* xr = x + (size_t)row * EMB_DIM;
        float bv = INFINITY;
        int   bk = 1 << 30;
        bool ovf = false;
#pragma unroll
        for (int li = 0; li < 4; li++)
            if (cnts[tid * 4 + li] > CAP) ovf = true;
        if (ovf) {
            // certified-margin overflow fallback (P ~ 0): full exact scan
            for (int k = 0; k < NUM_EMB; k++) {
                float dot = exact_dot(xr, emb + (size_t)k * EMB_DIM);
                float d = __fsub_rn(__fadd_rn(sxe, g_be[k]),
                                    __fmul_rn(2.0f, dot));
                if (d < bv || (d == bv && k < bk)) { bv = d; bk = k; }
            }
        } else {
#pragma unroll
            for (int li = 0; li < 4; li++) {
                const uint16_t* ls = cand + (tid * 4 + li) * CAP;
                const int nc = cnts[tid * 4 + li];
                for (int i = 0; i < nc; i++) {
                    const int k = ls[i];
                    float dot = exact_dot(xr, emb + (size_t)k * EMB_DIM);
                    float d = __fsub_rn(__fadd_rn(sxe, g_be[k]),
                                        __fmul_rn(2.0f, dot));
                    if (d < bv || (d == bv && k < bk)) { bv = d; bk = k; }
                }
            }
        }
        s_bk[tid] = bk;
        out[(size_t)OUT_ENC + (size_t)row * NUM_EMB + bk] = 1.0f;
        atomicAdd(&g_hist[bk], 1);   // integer atomic: deterministic
    }
    __syncthreads();

    // ---- cooperative coalesced quantized_st + loss (32-bit stores) ----
    double lsum = 0.0;
    float* oq = out + OUT_Q + (size_t)m0 * EMB_DIM;
    const float* xq = x + (size_t)m0 * EMB_DIM;
    for (int e = tid; e < BM * EMB_DIM; e += 256) {
        const int row = e >> 7;
        const int col = e & 127;
        const float xv = xq[e];
        const float qv = emb[(size_t)s_bk[row] * EMB_DIM + col];
        const float d  = __fsub_rn(qv, xv);
        oq[e] = __fadd_rn(xv, d);        // fl(x + fl(q-x)), exact STE math
        lsum += (double)d * (double)d;
    }
    lred[tid] = lsum;
    __syncthreads();
    for (int s = 128; s > 0; s >>= 1) {
        if (tid < s) lred[tid] += lred[tid + s];
        __syncthreads();
    }
    if (tid == 0) g_lpart[blockIdx.x] = lred[0];

    // ---- last block computes the scalars (fused finalize) ----
    __shared__ bool is_last;
    __threadfence();
    if (tid == 0) {
        unsigned v = atomicAdd(&g_done, 1u);
        is_last = (v == NBLK - 1);
    }
    __syncthreads();
    if (!is_last) return;

    double ent = 0.0;
#pragma unroll
    for (int b = 0; b < 4; b++) {
        double pr = (double)g_hist[tid * 4 + b] / (double)N_TOKENS;
        ent += pr * log(pr + 1e-10);
    }
    double ls = 0.0;
#pragma unroll
    for (int b = 0; b < 2; b++) ls += g_lpart[tid * 2 + b];
    lred[tid] = ent;
    lacc[tid] = ls;
    __syncthreads();
    for (int s = 128; s > 0; s >>= 1) {
        if (tid < s) { lred[tid] += lred[tid + s]; lacc[tid] += lacc[tid + s]; }
        __syncthreads();
    }
    if (tid == 0) {
        out[OUT_PERP] = (float)exp(-lred[0]);
        out[OUT_LOSS] = (float)(lacc[0] / ((double)N_TOKENS * (double)EMB_DIM));
    }
}

// ---------------------------------------------------------------------------
extern "C" void kernel_launch(void* const* d_in, const int* in_sizes, int n_in,
                              void* d_out, int out_size) {
    const float* x   = (const float*)d_in[0];   // inputs [65536,128]
    const float* emb = (const float*)d_in[1];   // emb_w  [1024,128]
    float* out = (float*)d_out;

    cudaFuncSetAttribute(vq_main_kernel,
                         cudaFuncAttributeMaxDynamicSharedMemorySize, DSMEM);
    vq_prep_kernel<<<NUM_EMB * 32 / 256, 256>>>(emb);
    vq_main_kernel<<<NBLK, 256, DSMEM>>>(x, emb, out);
}